// round 11
// baseline (speedup 1.0000x reference)
#include <cuda_runtime.h>
#include <cuda_fp16.h>
#include <math.h>
#include <stdint.h>

#define N_TOK 4096
#define H_DIM 1024
#define F_DIM 4096
#define N_EXP 8

#define BM 128
#define BN 256
#define BK 64
#define NTHREADS 256
#define NSTAGE 3
#define TILES_PER_E 32
#define NSPLIT 4
#define KSPLIT (F_DIM / NSPLIT)   // 1024

#define AH_STRIDE 72      // halfs: 64+8 pad -> 144B rows
#define BH_STRIDE 264     // halfs: 256+8 pad -> 528B rows
#define A_STAGE_B (BM * AH_STRIDE * 2)   // 18432 B
#define B_STAGE_B (BK * BH_STRIDE * 2)   // 33792 B
#define SMEM_BYTES (512 + NSTAGE * (A_STAGE_B + B_STAGE_B))   // 157184

#define WSZ ((size_t)N_EXP * H_DIM * F_DIM)

// Routing state + scratch (allocation-free: __device__ globals).
__device__ int    g_cnt[N_EXP];
__device__ int    g_off[N_EXP];
__device__ int    g_tok[N_EXP * N_TOK];
__device__ float  g_gw [N_EXP * N_TOK];
__device__ __half g_xh [(size_t)N_TOK * H_DIM];               // x  fp16
__device__ __half g_W1h[WSZ];                                  // W1 fp16 [E][H][F]
__device__ __half g_W2h[WSZ];                                  // W2 fp16 [E][F][H]
__device__ __half g_h  [(size_t)9216 * F_DIM];                // gelu(h) fp16

__device__ __forceinline__ void mma_f16(float c[4],
                                        uint32_t a0, uint32_t a1, uint32_t a2, uint32_t a3,
                                        uint32_t b0, uint32_t b1) {
    asm volatile(
        "mma.sync.aligned.m16n8k16.row.col.f32.f16.f16.f32 "
        "{%0,%1,%2,%3}, {%4,%5,%6,%7}, {%8,%9}, {%0,%1,%2,%3};\n"
        : "+f"(c[0]), "+f"(c[1]), "+f"(c[2]), "+f"(c[3])
        : "r"(a0), "r"(a1), "r"(a2), "r"(a3), "r"(b0), "r"(b1));
}
#define LDSM_X4(r, addr) \
    asm volatile("ldmatrix.sync.aligned.m8n8.x4.shared.b16 {%0,%1,%2,%3}, [%4];" \
        : "=r"((r)[0]), "=r"((r)[1]), "=r"((r)[2]), "=r"((r)[3]) : "r"(addr))
#define LDSM_X4_T(r, addr) \
    asm volatile("ldmatrix.sync.aligned.m8n8.x4.trans.shared.b16 {%0,%1,%2,%3}, [%4];" \
        : "=r"((r)[0]), "=r"((r)[1]), "=r"((r)[2]), "=r"((r)[3]) : "r"(addr))
#define CP_ASYNC16(dst, src) \
    asm volatile("cp.async.cg.shared.global [%0], [%1], 16;" :: "r"(dst), "l"(src) : "memory")
#define CP_COMMIT() asm volatile("cp.async.commit_group;" ::: "memory")
#define CP_WAIT1()  asm volatile("cp.async.wait_group 1;" ::: "memory")

__device__ __forceinline__ float gelu_exact(float v) {
    return 0.5f * v * (1.0f + erff(v * 0.70710678118654752f));
}

// ---------------- small kernels ----------------
// prep: zero counters + zero out + convert x to fp16
__global__ void prep_kernel(const float* __restrict__ x, float* __restrict__ out, int n) {
    int i = blockIdx.x * blockDim.x + threadIdx.x;
    if (i < N_EXP) g_cnt[i] = 0;
    int stride = gridDim.x * blockDim.x;
    for (int j = i; j < n; j += stride) out[j] = 0.0f;
    const int xf4 = N_TOK * H_DIM / 4;
    for (int j = i; j < xf4; j += stride) {
        float4 v = reinterpret_cast<const float4*>(x)[j];
        __half2 h0 = __floats2half2_rn(v.x, v.y);
        __half2 h1 = __floats2half2_rn(v.z, v.w);
        uint2 o = {*reinterpret_cast<uint32_t*>(&h0), *reinterpret_cast<uint32_t*>(&h1)};
        reinterpret_cast<uint2*>(g_xh)[j] = o;
    }
}

// fused W1+W2 fp32->fp16, 8 elems/thread
__global__ void wconv_kernel(const float* __restrict__ W1, const float* __restrict__ W2) {
    size_t i = ((size_t)blockIdx.x * blockDim.x + threadIdx.x) * 2;
    size_t half_n = WSZ / 4;
    const float4* src; uint2* dst;
    if (i < half_n) {
        src = reinterpret_cast<const float4*>(W1) + i;
        dst = reinterpret_cast<uint2*>(g_W1h) + i;
    } else {
        src = reinterpret_cast<const float4*>(W2) + (i - half_n);
        dst = reinterpret_cast<uint2*>(g_W2h) + (i - half_n);
    }
#pragma unroll
    for (int u = 0; u < 2; u++) {
        float4 v = src[u];
        __half2 h0 = __floats2half2_rn(v.x, v.y);
        __half2 h1 = __floats2half2_rn(v.z, v.w);
        uint2 o = {*reinterpret_cast<uint32_t*>(&h0), *reinterpret_cast<uint32_t*>(&h1)};
        dst[u] = o;
    }
}

__global__ void gate_kernel(const float* __restrict__ x,
                            const float* __restrict__ Wg,
                            const float* __restrict__ bg) {
    int warp = threadIdx.x >> 5, lane = threadIdx.x & 31;
    int n = blockIdx.x * (blockDim.x >> 5) + warp;
    if (n >= N_TOK) return;
    float acc[N_EXP];
#pragma unroll
    for (int e = 0; e < N_EXP; e++) acc[e] = 0.0f;
    const float* xr = x + (size_t)n * H_DIM;
    for (int h = lane; h < H_DIM; h += 32) {
        float xv = xr[h];
        const float4 w0 = *reinterpret_cast<const float4*>(Wg + h * N_EXP);
        const float4 w1 = *reinterpret_cast<const float4*>(Wg + h * N_EXP + 4);
        acc[0] += xv * w0.x; acc[1] += xv * w0.y; acc[2] += xv * w0.z; acc[3] += xv * w0.w;
        acc[4] += xv * w1.x; acc[5] += xv * w1.y; acc[6] += xv * w1.z; acc[7] += xv * w1.w;
    }
#pragma unroll
    for (int e = 0; e < N_EXP; e++)
#pragma unroll
        for (int o = 16; o > 0; o >>= 1) acc[e] += __shfl_xor_sync(0xffffffffu, acc[e], o);
    if (lane == 0) {
        float p[N_EXP], m = -1e30f, s = 0.0f;
#pragma unroll
        for (int e = 0; e < N_EXP; e++) { p[e] = acc[e] + bg[e]; m = fmaxf(m, p[e]); }
#pragma unroll
        for (int e = 0; e < N_EXP; e++) { p[e] = expf(p[e] - m); s += p[e]; }
        float inv = 1.0f / s;
#pragma unroll
        for (int e = 0; e < N_EXP; e++) p[e] *= inv;
        int i0 = 0;
#pragma unroll
        for (int e = 1; e < N_EXP; e++) if (p[e] > p[i0]) i0 = e;
        int i1 = (i0 == 0) ? 1 : 0;
#pragma unroll
        for (int e = 0; e < N_EXP; e++) if (e != i0 && p[e] > p[i1]) i1 = e;
        int p0 = atomicAdd(&g_cnt[i0], 1);
        g_tok[i0 * N_TOK + p0] = n;  g_gw[i0 * N_TOK + p0] = p[i0];
        int p1 = atomicAdd(&g_cnt[i1], 1);
        g_tok[i1 * N_TOK + p1] = n;  g_gw[i1 * N_TOK + p1] = p[i1];
    }
}

__global__ void offsets_kernel() {
    if (threadIdx.x == 0 && blockIdx.x == 0) {
        int off = 0;
        for (int e = 0; e < N_EXP; e++) {
            g_off[e] = off;
            off += ((g_cnt[e] + BM - 1) / BM) * BM;
        }
    }
}

// ---------------------------------------------------------------------------
// GEMM core: 8 warps of 64x64, fp16 m16n8k16, ldmatrix operands, BK=64
// ---------------------------------------------------------------------------
#define DECLARE_TILE_CTX() \
    int tid = threadIdx.x, warp = tid >> 5, lane = tid & 31; \
    int gid = lane >> 2, tig = lane & 3; \
    int wm = (warp >> 2) * 64, wn = (warp & 3) * 64; \
    int t8 = lane & 7, ta = lane >> 3; \
    uint32_t aoff = (uint32_t)(wm + (ta & 1) * 8 + t8) * (AH_STRIDE * 2) + (ta >> 1) * 16; \
    uint32_t boff = (uint32_t)((ta & 1) * 8 + t8) * (BH_STRIDE * 2) + (ta >> 1) * 16 + wn * 2; \
    float acc[4][8][4]; \
    _Pragma("unroll") for (int mf = 0; mf < 4; mf++) \
    _Pragma("unroll") for (int nf = 0; nf < 8; nf++) \
    _Pragma("unroll") for (int r = 0; r < 4; r++) acc[mf][nf][r] = 0.0f;

#define COMPUTE_KTILE(aBase, bBase) do { \
    _Pragma("unroll") \
    for (int ks = 0; ks < 4; ks++) { \
        uint32_t a[4][4], b[4][4]; \
        _Pragma("unroll") \
        for (int mf = 0; mf < 4; mf++) \
            LDSM_X4(a[mf], (aBase) + aoff + (uint32_t)mf * 16 * (AH_STRIDE * 2) + ks * 32); \
        _Pragma("unroll") \
        for (int p = 0; p < 4; p++) \
            LDSM_X4_T(b[p], (bBase) + boff + (uint32_t)p * 32 + (uint32_t)ks * 16 * (BH_STRIDE * 2)); \
        _Pragma("unroll") \
        for (int mf = 0; mf < 4; mf++) \
        _Pragma("unroll") \
        for (int nf = 0; nf < 8; nf++) \
            mma_f16(acc[mf][nf], a[mf][0], a[mf][1], a[mf][2], a[mf][3], \
                    b[nf >> 1][(nf & 1) * 2], b[nf >> 1][(nf & 1) * 2 + 1]); \
    } } while (0)

// ---------------------------------------------------------------------------
// ffn1: g_h = fp16(gelu(X_gathered @ W1[e] + b1[e]))   K = H_DIM
// ---------------------------------------------------------------------------
__global__ __launch_bounds__(NTHREADS, 1) void ffn1_kernel(const float* __restrict__ b1) {
    extern __shared__ char dsm[];
    int* toks = (int*)dsm;
    uint32_t As0 = (uint32_t)__cvta_generic_to_shared(dsm + 512);
    uint32_t Bs0 = (uint32_t)__cvta_generic_to_shared(dsm + 512 + NSTAGE * A_STAGE_B);

    int e    = blockIdx.y >> 5;
    int tile = blockIdx.y & 31;
    int row0 = tile * BM;
    int cnt  = g_cnt[e];
    if (row0 >= cnt) return;
    int off  = g_off[e];
    int col0 = blockIdx.x * BN;
    const __half* B = g_W1h + (size_t)e * H_DIM * F_DIM;

    DECLARE_TILE_CTX();

    if (tid < BM) {
        int r = row0 + tid; if (r >= cnt) r = cnt - 1;
        toks[tid] = g_tok[e * N_TOK + r];
    }
    __syncthreads();

    uint32_t a_dst[4]; const __half* a_src[4];
#pragma unroll
    for (int i = 0; i < 4; i++) {
        int q = tid + i * 256; int r = q >> 3, c = q & 7;
        a_dst[i] = As0 + (uint32_t)r * (AH_STRIDE * 2) + c * 16;
        a_src[i] = g_xh + (size_t)toks[r] * H_DIM + c * 8;
    }
    uint32_t b_dst[8]; const __half* b_src[8];
#pragma unroll
    for (int i = 0; i < 8; i++) {
        int q = tid + i * 256; int kk = q >> 5, c = q & 31;
        b_dst[i] = Bs0 + (uint32_t)kk * (BH_STRIDE * 2) + c * 16;
        b_src[i] = B + (size_t)kk * F_DIM + col0 + c * 8;
    }

#define FILL1(st, ktile) do { \
    _Pragma("unroll") for (int i = 0; i < 4; i++) \
        CP_ASYNC16(a_dst[i] + (st) * A_STAGE_B, a_src[i] + (ktile) * BK); \
    _Pragma("unroll") for (int i = 0; i < 8; i++) \
        CP_ASYNC16(b_dst[i] + (st) * B_STAGE_B, b_src[i] + (size_t)(ktile) * BK * F_DIM); \
    CP_COMMIT(); } while (0)

    FILL1(0, 0);
    FILL1(1, 1);
    const int NKT = H_DIM / BK;
#pragma unroll 1
    for (int kt = 0; kt < NKT; kt++) {
        CP_WAIT1();
        __syncthreads();
        int nk = kt + 2;
        if (nk < NKT) FILL1(nk % NSTAGE, nk);
        int cs = kt % NSTAGE;
        COMPUTE_KTILE(As0 + cs * A_STAGE_B, Bs0 + cs * B_STAGE_B);
    }

#pragma unroll
    for (int mf = 0; mf < 4; mf++) {
#pragma unroll
        for (int r2 = 0; r2 < 2; r2++) {
            int m = wm + mf * 16 + gid + r2 * 8;
            __half* hrow = g_h + (size_t)(off + row0 + m) * F_DIM + col0;
#pragma unroll
            for (int nf = 0; nf < 8; nf++) {
                int c = wn + nf * 8 + tig * 2;
                float v0 = acc[mf][nf][r2 * 2 + 0] + b1[e * F_DIM + col0 + c];
                float v1 = acc[mf][nf][r2 * 2 + 1] + b1[e * F_DIM + col0 + c + 1];
                __half2 g = __floats2half2_rn(gelu_exact(v0), gelu_exact(v1));
                *reinterpret_cast<uint32_t*>(hrow + c) = *reinterpret_cast<uint32_t*>(&g);
            }
        }
    }
}

// ---------------------------------------------------------------------------
// ffn2 (split-K): out[token] += gw * (h @ W2[e] + b2[e]),  K split NSPLIT ways
// ---------------------------------------------------------------------------
__global__ __launch_bounds__(NTHREADS, 1) void ffn2_kernel(
    const float* __restrict__ b2, float* __restrict__ out) {
    extern __shared__ char dsm[];
    uint32_t As0 = (uint32_t)__cvta_generic_to_shared(dsm + 512);
    uint32_t Bs0 = (uint32_t)__cvta_generic_to_shared(dsm + 512 + NSTAGE * A_STAGE_B);

    int e    = blockIdx.y >> 5;
    int tile = blockIdx.y & 31;
    int split = blockIdx.z;
    int row0 = tile * BM;
    int cnt  = g_cnt[e];
    if (row0 >= cnt) return;
    int off  = g_off[e];
    int col0 = blockIdx.x * BN;
    const __half* B = g_W2h + (size_t)e * F_DIM * H_DIM + (size_t)split * KSPLIT * H_DIM;
    const __half* A = g_h + (size_t)(off + row0) * F_DIM + split * KSPLIT;

    DECLARE_TILE_CTX();

    uint32_t a_dst[4]; const __half* a_src[4];
#pragma unroll
    for (int i = 0; i < 4; i++) {
        int q = tid + i * 256; int r = q >> 3, c = q & 7;
        a_dst[i] = As0 + (uint32_t)r * (AH_STRIDE * 2) + c * 16;
        a_src[i] = A + (size_t)r * F_DIM + c * 8;
    }
    uint32_t b_dst[8]; const __half* b_src[8];
#pragma unroll
    for (int i = 0; i < 8; i++) {
        int q = tid + i * 256; int kk = q >> 5, c = q & 31;
        b_dst[i] = Bs0 + (uint32_t)kk * (BH_STRIDE * 2) + c * 16;
        b_src[i] = B + (size_t)kk * H_DIM + col0 + c * 8;
    }

#define FILL2(st, ktile) do { \
    _Pragma("unroll") for (int i = 0; i < 4; i++) \
        CP_ASYNC16(a_dst[i] + (st) * A_STAGE_B, a_src[i] + (ktile) * BK); \
    _Pragma("unroll") for (int i = 0; i < 8; i++) \
        CP_ASYNC16(b_dst[i] + (st) * B_STAGE_B, b_src[i] + (size_t)(ktile) * BK * H_DIM); \
    CP_COMMIT(); } while (0)

    FILL2(0, 0);
    FILL2(1, 1);
    const int NKT = KSPLIT / BK;   // 16
#pragma unroll 1
    for (int kt = 0; kt < NKT; kt++) {
        CP_WAIT1();
        __syncthreads();
        int nk = kt + 2;
        if (nk < NKT) FILL2(nk % NSTAGE, nk);
        int cs = kt % NSTAGE;
        COMPUTE_KTILE(As0 + cs * A_STAGE_B, Bs0 + cs * B_STAGE_B);
    }

    // epilogue: (bias only on split 0), gate weight, atomic scatter
#pragma unroll
    for (int mf = 0; mf < 4; mf++) {
#pragma unroll
        for (int r2 = 0; r2 < 2; r2++) {
            int m = wm + mf * 16 + gid + r2 * 8;
            int r = row0 + m;
            if (r < cnt) {
                int   token = g_tok[e * N_TOK + r];
                float gw    = g_gw [e * N_TOK + r];
                float* orow = out + (size_t)token * H_DIM + col0;
#pragma unroll
                for (int nf = 0; nf < 8; nf++) {
                    int c = wn + nf * 8 + tig * 2;
                    float bb0 = (split == 0) ? b2[e * H_DIM + col0 + c]     : 0.0f;
                    float bb1 = (split == 0) ? b2[e * H_DIM + col0 + c + 1] : 0.0f;
                    atomicAdd(orow + c,     gw * (acc[mf][nf][r2 * 2 + 0] + bb0));
                    atomicAdd(orow + c + 1, gw * (acc[mf][nf][r2 * 2 + 1] + bb1));
                }
            }
        }
    }
}

extern "C" void kernel_launch(void* const* d_in, const int* in_sizes, int n_in,
                              void* d_out, int out_size) {
    const float* x  = (const float*)d_in[0];
    const float* W1 = (const float*)d_in[1];
    const float* b1 = (const float*)d_in[2];
    const float* W2 = (const float*)d_in[3];
    const float* b2 = (const float*)d_in[4];
    const float* Wg = (const float*)d_in[5];
    const float* bg = (const float*)d_in[6];
    float* out = (float*)d_out;

    cudaFuncSetAttribute(ffn1_kernel, cudaFuncAttributeMaxDynamicSharedMemorySize, SMEM_BYTES);
    cudaFuncSetAttribute(ffn2_kernel, cudaFuncAttributeMaxDynamicSharedMemorySize, SMEM_BYTES);

    prep_kernel<<<1024, 256>>>(x, out, out_size);
    gate_kernel<<<N_TOK / 8, 256>>>(x, Wg, bg);
    offsets_kernel<<<1, 1>>>();
    wconv_kernel<<<(2 * WSZ / 8) / 256, 256>>>(W1, W2);
    ffn1_kernel<<<dim3(F_DIM / BN, N_EXP * TILES_PER_E), NTHREADS, SMEM_BYTES>>>(b1);
    ffn2_kernel<<<dim3(H_DIM / BN, N_EXP * TILES_PER_E, NSPLIT), NTHREADS, SMEM_BYTES>>>(b2, out);
}

// round 14
// speedup vs baseline: 1.0281x; 1.0281x over previous
#include <cuda_runtime.h>
#include <cuda_fp16.h>
#include <math.h>
#include <stdint.h>

#define N_TOK 4096
#define H_DIM 1024
#define F_DIM 4096
#define N_EXP 8

#define BM 128
#define BN 256
#define BK 64
#define NTHREADS 256
#define NSTAGE 3
#define TILES_PER_E 32

#define AH_STRIDE 72      // halfs: 64+8 pad -> 144B rows
#define BH_STRIDE 264     // halfs: 256+8 pad -> 528B rows
#define A_STAGE_B (BM * AH_STRIDE * 2)   // 18432 B
#define B_STAGE_B (BK * BH_STRIDE * 2)   // 33792 B
#define SMEM_BYTES (512 + NSTAGE * (A_STAGE_B + B_STAGE_B))   // 157184

#define WSZ ((size_t)N_EXP * H_DIM * F_DIM)
#define WQ_CHUNK 2048                    // float4s per work-queue chunk (8/thread)
#define WQ_NCHUNK ((int)((WSZ / 4) / WQ_CHUNK))   // 4096

// Routing state + scratch (allocation-free: __device__ globals).
__device__ int    g_cnt[N_EXP];
__device__ int    g_off[N_EXP];
__device__ int    g_wq;                                        // W2-convert work queue
__device__ int    g_tok[N_EXP * N_TOK];
__device__ float  g_gw [N_EXP * N_TOK];
__device__ __half g_xh [(size_t)N_TOK * H_DIM];               // x  fp16
__device__ __half g_W1h[WSZ];                                  // W1 fp16 [E][H][F]
__device__ __half g_W2h[WSZ];                                  // W2 fp16 [E][F][H]
__device__ __half g_h  [(size_t)9216 * F_DIM];                // gelu(h) fp16

__device__ __forceinline__ void mma_f16(float c[4],
                                        uint32_t a0, uint32_t a1, uint32_t a2, uint32_t a3,
                                        uint32_t b0, uint32_t b1) {
    asm volatile(
        "mma.sync.aligned.m16n8k16.row.col.f32.f16.f16.f32 "
        "{%0,%1,%2,%3}, {%4,%5,%6,%7}, {%8,%9}, {%0,%1,%2,%3};\n"
        : "+f"(c[0]), "+f"(c[1]), "+f"(c[2]), "+f"(c[3])
        : "r"(a0), "r"(a1), "r"(a2), "r"(a3), "r"(b0), "r"(b1));
}
#define LDSM_X4(r, addr) \
    asm volatile("ldmatrix.sync.aligned.m8n8.x4.shared.b16 {%0,%1,%2,%3}, [%4];" \
        : "=r"((r)[0]), "=r"((r)[1]), "=r"((r)[2]), "=r"((r)[3]) : "r"(addr))
#define LDSM_X4_T(r, addr) \
    asm volatile("ldmatrix.sync.aligned.m8n8.x4.trans.shared.b16 {%0,%1,%2,%3}, [%4];" \
        : "=r"((r)[0]), "=r"((r)[1]), "=r"((r)[2]), "=r"((r)[3]) : "r"(addr))
#define CP_ASYNC16(dst, src) \
    asm volatile("cp.async.cg.shared.global [%0], [%1], 16;" :: "r"(dst), "l"(src) : "memory")
#define CP_COMMIT() asm volatile("cp.async.commit_group;" ::: "memory")
#define CP_WAIT1()  asm volatile("cp.async.wait_group 1;" ::: "memory")

__device__ __forceinline__ float gelu_exact(float v) {
    return 0.5f * v * (1.0f + erff(v * 0.70710678118654752f));
}
__device__ __forceinline__ uint2 f4_to_h4(float4 v) {
    __half2 h0 = __floats2half2_rn(v.x, v.y);
    __half2 h1 = __floats2half2_rn(v.z, v.w);
    return {*reinterpret_cast<uint32_t*>(&h0), *reinterpret_cast<uint32_t*>(&h1)};
}

// ---------------- small kernels ----------------
// prep: zero counters + work queue + out, convert x to fp16
__global__ void prep_kernel(const float* __restrict__ x, float* __restrict__ out, int n) {
    int i = blockIdx.x * blockDim.x + threadIdx.x;
    if (i < N_EXP) g_cnt[i] = 0;
    if (i == N_EXP) g_wq = 0;
    int stride = gridDim.x * blockDim.x;
    for (int j = i; j < n; j += stride) out[j] = 0.0f;
    const int xf4 = N_TOK * H_DIM / 4;
    for (int j = i; j < xf4; j += stride)
        reinterpret_cast<uint2*>(g_xh)[j] = f4_to_h4(reinterpret_cast<const float4*>(x)[j]);
}

// W1 only fp32->fp16, 8 elems/thread
__global__ void wconv_kernel(const float* __restrict__ W1) {
    size_t i = ((size_t)blockIdx.x * blockDim.x + threadIdx.x) * 2;
#pragma unroll
    for (int u = 0; u < 2; u++)
        reinterpret_cast<uint2*>(g_W1h)[i + u] =
            f4_to_h4(reinterpret_cast<const float4*>(W1)[i + u]);
}

__global__ void gate_kernel(const float* __restrict__ x,
                            const float* __restrict__ Wg,
                            const float* __restrict__ bg) {
    int warp = threadIdx.x >> 5, lane = threadIdx.x & 31;
    int n = blockIdx.x * (blockDim.x >> 5) + warp;
    if (n >= N_TOK) return;
    float acc[N_EXP];
#pragma unroll
    for (int e = 0; e < N_EXP; e++) acc[e] = 0.0f;
    const float* xr = x + (size_t)n * H_DIM;
    for (int h = lane; h < H_DIM; h += 32) {
        float xv = xr[h];
        const float4 w0 = *reinterpret_cast<const float4*>(Wg + h * N_EXP);
        const float4 w1 = *reinterpret_cast<const float4*>(Wg + h * N_EXP + 4);
        acc[0] += xv * w0.x; acc[1] += xv * w0.y; acc[2] += xv * w0.z; acc[3] += xv * w0.w;
        acc[4] += xv * w1.x; acc[5] += xv * w1.y; acc[6] += xv * w1.z; acc[7] += xv * w1.w;
    }
#pragma unroll
    for (int e = 0; e < N_EXP; e++)
#pragma unroll
        for (int o = 16; o > 0; o >>= 1) acc[e] += __shfl_xor_sync(0xffffffffu, acc[e], o);
    if (lane == 0) {
        float p[N_EXP], m = -1e30f, s = 0.0f;
#pragma unroll
        for (int e = 0; e < N_EXP; e++) { p[e] = acc[e] + bg[e]; m = fmaxf(m, p[e]); }
#pragma unroll
        for (int e = 0; e < N_EXP; e++) { p[e] = expf(p[e] - m); s += p[e]; }
        float inv = 1.0f / s;
#pragma unroll
        for (int e = 0; e < N_EXP; e++) p[e] *= inv;
        int i0 = 0;
#pragma unroll
        for (int e = 1; e < N_EXP; e++) if (p[e] > p[i0]) i0 = e;
        int i1 = (i0 == 0) ? 1 : 0;
#pragma unroll
        for (int e = 0; e < N_EXP; e++) if (e != i0 && p[e] > p[i1]) i1 = e;
        int p0 = atomicAdd(&g_cnt[i0], 1);
        g_tok[i0 * N_TOK + p0] = n;  g_gw[i0 * N_TOK + p0] = p[i0];
        int p1 = atomicAdd(&g_cnt[i1], 1);
        g_tok[i1 * N_TOK + p1] = n;  g_gw[i1 * N_TOK + p1] = p[i1];
    }
}

__global__ void offsets_kernel() {
    if (threadIdx.x == 0 && blockIdx.x == 0) {
        int off = 0;
        for (int e = 0; e < N_EXP; e++) {
            g_off[e] = off;
            off += ((g_cnt[e] + BM - 1) / BM) * BM;
        }
    }
}

// ---------------------------------------------------------------------------
// GEMM core: 8 warps of 64x64, fp16 m16n8k16, ldmatrix operands, BK=64
// NOTE: `tid` must be declared by the caller before this macro.
// ---------------------------------------------------------------------------
#define DECLARE_TILE_CTX() \
    int warp = tid >> 5, lane = tid & 31; \
    int gid = lane >> 2, tig = lane & 3; \
    int wm = (warp >> 2) * 64, wn = (warp & 3) * 64; \
    int t8 = lane & 7, ta = lane >> 3; \
    uint32_t aoff = (uint32_t)(wm + (ta & 1) * 8 + t8) * (AH_STRIDE * 2) + (ta >> 1) * 16; \
    uint32_t boff = (uint32_t)((ta & 1) * 8 + t8) * (BH_STRIDE * 2) + (ta >> 1) * 16 + wn * 2; \
    float acc[4][8][4]; \
    _Pragma("unroll") for (int mf = 0; mf < 4; mf++) \
    _Pragma("unroll") for (int nf = 0; nf < 8; nf++) \
    _Pragma("unroll") for (int r = 0; r < 4; r++) acc[mf][nf][r] = 0.0f;

#define COMPUTE_KTILE(aBase, bBase) do { \
    _Pragma("unroll") \
    for (int ks = 0; ks < 4; ks++) { \
        uint32_t a[4][4], b[4][4]; \
        _Pragma("unroll") \
        for (int mf = 0; mf < 4; mf++) \
            LDSM_X4(a[mf], (aBase) + aoff + (uint32_t)mf * 16 * (AH_STRIDE * 2) + ks * 32); \
        _Pragma("unroll") \
        for (int p = 0; p < 4; p++) \
            LDSM_X4_T(b[p], (bBase) + boff + (uint32_t)p * 32 + (uint32_t)ks * 16 * (BH_STRIDE * 2)); \
        _Pragma("unroll") \
        for (int mf = 0; mf < 4; mf++) \
        _Pragma("unroll") \
        for (int nf = 0; nf < 8; nf++) \
            mma_f16(acc[mf][nf], a[mf][0], a[mf][1], a[mf][2], a[mf][3], \
                    b[nf >> 1][(nf & 1) * 2], b[nf >> 1][(nf & 1) * 2 + 1]); \
    } } while (0)

// ---------------------------------------------------------------------------
// ffn1: g_h = fp16(gelu(X_gathered @ W1[e] + b1[e]))   K = H_DIM
// Idle blocks (row0 >= cnt) convert W2 fp32->fp16 via work queue instead.
// ---------------------------------------------------------------------------
__global__ __launch_bounds__(NTHREADS, 1) void ffn1_kernel(
    const float* __restrict__ b1, const float* __restrict__ W2) {
    extern __shared__ char dsm[];
    int* toks = (int*)dsm;
    uint32_t As0 = (uint32_t)__cvta_generic_to_shared(dsm + 512);
    uint32_t Bs0 = (uint32_t)__cvta_generic_to_shared(dsm + 512 + NSTAGE * A_STAGE_B);

    int e    = blockIdx.y >> 5;
    int tile = blockIdx.y & 31;
    int row0 = tile * BM;
    int cnt  = g_cnt[e];
    int tid  = threadIdx.x;

    if (row0 >= cnt) {
        // idle block: drain the W2 conversion queue (hidden under GEMM blocks)
        __shared__ int s_chunk;
        const float4* src = reinterpret_cast<const float4*>(W2);
        uint2* dst = reinterpret_cast<uint2*>(g_W2h);
        for (;;) {
            if (tid == 0) s_chunk = atomicAdd(&g_wq, 1);
            __syncthreads();
            int c = s_chunk;
            __syncthreads();
            if (c >= WQ_NCHUNK) return;
            size_t base = (size_t)c * WQ_CHUNK + tid;
#pragma unroll
            for (int u = 0; u < WQ_CHUNK / NTHREADS; u++)
                dst[base + u * NTHREADS] = f4_to_h4(src[base + u * NTHREADS]);
        }
    }

    int off  = g_off[e];
    int col0 = blockIdx.x * BN;
    const __half* B = g_W1h + (size_t)e * H_DIM * F_DIM;

    DECLARE_TILE_CTX();

    if (tid < BM) {
        int r = row0 + tid; if (r >= cnt) r = cnt - 1;
        toks[tid] = g_tok[e * N_TOK + r];
    }
    __syncthreads();

    uint32_t a_dst[4]; const __half* a_src[4];
#pragma unroll
    for (int i = 0; i < 4; i++) {
        int q = tid + i * 256; int r = q >> 3, c = q & 7;
        a_dst[i] = As0 + (uint32_t)r * (AH_STRIDE * 2) + c * 16;
        a_src[i] = g_xh + (size_t)toks[r] * H_DIM + c * 8;
    }
    uint32_t b_dst[8]; const __half* b_src[8];
#pragma unroll
    for (int i = 0; i < 8; i++) {
        int q = tid + i * 256; int kk = q >> 5, c = q & 31;
        b_dst[i] = Bs0 + (uint32_t)kk * (BH_STRIDE * 2) + c * 16;
        b_src[i] = B + (size_t)kk * F_DIM + col0 + c * 8;
    }

#define FILL1(st, ktile) do { \
    _Pragma("unroll") for (int i = 0; i < 4; i++) \
        CP_ASYNC16(a_dst[i] + (st) * A_STAGE_B, a_src[i] + (ktile) * BK); \
    _Pragma("unroll") for (int i = 0; i < 8; i++) \
        CP_ASYNC16(b_dst[i] + (st) * B_STAGE_B, b_src[i] + (size_t)(ktile) * BK * F_DIM); \
    CP_COMMIT(); } while (0)

    FILL1(0, 0);
    FILL1(1, 1);
    const int NKT = H_DIM / BK;
#pragma unroll 1
    for (int kt = 0; kt < NKT; kt++) {
        CP_WAIT1();
        __syncthreads();
        int nk = kt + 2;
        if (nk < NKT) FILL1(nk % NSTAGE, nk);
        int cs = kt % NSTAGE;
        COMPUTE_KTILE(As0 + cs * A_STAGE_B, Bs0 + cs * B_STAGE_B);
    }

#pragma unroll
    for (int mf = 0; mf < 4; mf++) {
#pragma unroll
        for (int r2 = 0; r2 < 2; r2++) {
            int m = wm + mf * 16 + gid + r2 * 8;
            __half* hrow = g_h + (size_t)(off + row0 + m) * F_DIM + col0;
#pragma unroll
            for (int nf = 0; nf < 8; nf++) {
                int c = wn + nf * 8 + tig * 2;
                float v0 = acc[mf][nf][r2 * 2 + 0] + b1[e * F_DIM + col0 + c];
                float v1 = acc[mf][nf][r2 * 2 + 1] + b1[e * F_DIM + col0 + c + 1];
                __half2 g = __floats2half2_rn(gelu_exact(v0), gelu_exact(v1));
                *reinterpret_cast<uint32_t*>(hrow + c) = *reinterpret_cast<uint32_t*>(&g);
            }
        }
    }
}

// ---------------------------------------------------------------------------
// ffn2: out[token] += gw * (h @ W2[e] + b2[e])   K = F_DIM
// ---------------------------------------------------------------------------
__global__ __launch_bounds__(NTHREADS, 1) void ffn2_kernel(
    const float* __restrict__ b2, float* __restrict__ out) {
    extern __shared__ char dsm[];
    uint32_t As0 = (uint32_t)__cvta_generic_to_shared(dsm + 512);
    uint32_t Bs0 = (uint32_t)__cvta_generic_to_shared(dsm + 512 + NSTAGE * A_STAGE_B);

    int e    = blockIdx.y >> 5;
    int tile = blockIdx.y & 31;
    int row0 = tile * BM;
    int cnt  = g_cnt[e];
    if (row0 >= cnt) return;
    int off  = g_off[e];
    int col0 = blockIdx.x * BN;
    const __half* B = g_W2h + (size_t)e * F_DIM * H_DIM;
    const __half* A = g_h + (size_t)(off + row0) * F_DIM;
    int tid  = threadIdx.x;

    DECLARE_TILE_CTX();

    uint32_t a_dst[4]; const __half* a_src[4];
#pragma unroll
    for (int i = 0; i < 4; i++) {
        int q = tid + i * 256; int r = q >> 3, c = q & 7;
        a_dst[i] = As0 + (uint32_t)r * (AH_STRIDE * 2) + c * 16;
        a_src[i] = A + (size_t)r * F_DIM + c * 8;
    }
    uint32_t b_dst[8]; const __half* b_src[8];
#pragma unroll
    for (int i = 0; i < 8; i++) {
        int q = tid + i * 256; int kk = q >> 5, c = q & 31;
        b_dst[i] = Bs0 + (uint32_t)kk * (BH_STRIDE * 2) + c * 16;
        b_src[i] = B + (size_t)kk * H_DIM + col0 + c * 8;
    }

#define FILL2(st, ktile) do { \
    _Pragma("unroll") for (int i = 0; i < 4; i++) \
        CP_ASYNC16(a_dst[i] + (st) * A_STAGE_B, a_src[i] + (ktile) * BK); \
    _Pragma("unroll") for (int i = 0; i < 8; i++) \
        CP_ASYNC16(b_dst[i] + (st) * B_STAGE_B, b_src[i] + (size_t)(ktile) * BK * H_DIM); \
    CP_COMMIT(); } while (0)

    FILL2(0, 0);
    FILL2(1, 1);
    const int NKT = F_DIM / BK;
#pragma unroll 1
    for (int kt = 0; kt < NKT; kt++) {
        CP_WAIT1();
        __syncthreads();
        int nk = kt + 2;
        if (nk < NKT) FILL2(nk % NSTAGE, nk);
        int cs = kt % NSTAGE;
        COMPUTE_KTILE(As0 + cs * A_STAGE_B, Bs0 + cs * B_STAGE_B);
    }

#pragma unroll
    for (int mf = 0; mf < 4; mf++) {
#pragma unroll
        for (int r2 = 0; r2 < 2; r2++) {
            int m = wm + mf * 16 + gid + r2 * 8;
            int r = row0 + m;
            if (r < cnt) {
                int   token = g_tok[e * N_TOK + r];
                float gw    = g_gw [e * N_TOK + r];
                float* orow = out + (size_t)token * H_DIM + col0;
#pragma unroll
                for (int nf = 0; nf < 8; nf++) {
                    int c = wn + nf * 8 + tig * 2;
                    float v0 = acc[mf][nf][r2 * 2 + 0] + b2[e * H_DIM + col0 + c];
                    float v1 = acc[mf][nf][r2 * 2 + 1] + b2[e * H_DIM + col0 + c + 1];
                    atomicAdd(orow + c,     gw * v0);
                    atomicAdd(orow + c + 1, gw * v1);
                }
            }
        }
    }
}

extern "C" void kernel_launch(void* const* d_in, const int* in_sizes, int n_in,
                              void* d_out, int out_size) {
    const float* x  = (const float*)d_in[0];
    const float* W1 = (const float*)d_in[1];
    const float* b1 = (const float*)d_in[2];
    const float* W2 = (const float*)d_in[3];
    const float* b2 = (const float*)d_in[4];
    const float* Wg = (const float*)d_in[5];
    const float* bg = (const float*)d_in[6];
    float* out = (float*)d_out;

    cudaFuncSetAttribute(ffn1_kernel, cudaFuncAttributeMaxDynamicSharedMemorySize, SMEM_BYTES);
    cudaFuncSetAttribute(ffn2_kernel, cudaFuncAttributeMaxDynamicSharedMemorySize, SMEM_BYTES);

    prep_kernel<<<1024, 256>>>(x, out, out_size);
    gate_kernel<<<N_TOK / 8, 256>>>(x, Wg, bg);
    offsets_kernel<<<1, 1>>>();
    wconv_kernel<<<(WSZ / 8) / 256, 256>>>(W1);
    ffn1_kernel<<<dim3(F_DIM / BN, N_EXP * TILES_PER_E), NTHREADS, SMEM_BYTES>>>(b1, W2);
    ffn2_kernel<<<dim3(H_DIM / BN, N_EXP * TILES_PER_E), NTHREADS, SMEM_BYTES>>>(b2, out);
}